// round 7
// baseline (speedup 1.0000x reference)
#include <cuda_runtime.h>
#include <cstdint>

// ---------------- problem constants ----------------
#define AN      3
#define NC      80
#define NCH     85          // C+5
#define HH      52
#define WW      52
#define HWSZ    (HH*WW)     // 2704
#define MAXN    256
#define ROWF4   13          // 52 floats / 4
#define VECS    (NCH*ROWF4) // 1105 float4 per (b,a,h) row
#define TILEF   (NCH*WW)    // 4420 floats per row
#define TMAIN   512
#define MAXBLK  1280
#define CELLS   (16*AN*HWSZ)
#define BULKN   (2*80*13)   // 2080 bulk float4 units (c>=5)
#define SPECN   (2*5*13)    // 130 special float4 units (c<5)
#define SPEC0   (TMAIN - SPECN)  // 382: first special thread
#define TILE_BYTES (2*TILEF*4)   // 35360

__constant__ float c_aw[AN] = {10.f, 16.f, 33.f};
__constant__ float c_ah[AN] = {13.f, 30.f, 23.f};

// ---------------- device scratch (no allocations allowed) ----------------
__device__ int    g_mask_i[CELLS];
__device__ float  g_psum[MAXBLK];
__device__ int    g_cell[MAXN];
__device__ float  g_tx[MAXN], g_ty[MAXN], g_tw[MAXN], g_th[MAXN];
__device__ int    g_lab[MAXN];
__device__ int    g_mcell[4*MAXN];
__device__ unsigned char g_mwin[4*MAXN];
__device__ unsigned char g_owin[MAXN];
__device__ int    g_mcnt;
__device__ unsigned int g_done;   // zero at load; winner resets each replay

// ---- fast math helpers ----
#define L2E 1.4426950408889634f
#define LN2 0.6931471805599453f

__device__ __forceinline__ float fex2(float x) {
    float r; asm("ex2.approx.ftz.f32 %0, %1;" : "=f"(r) : "f"(x)); return r;
}
__device__ __forceinline__ float frcp(float x) {
    float r; asm("rcp.approx.ftz.f32 %0, %1;" : "=f"(r) : "f"(x)); return r;
}
__device__ __forceinline__ float flg2(float x) {
    float r; asm("lg2.approx.ftz.f32 %0, %1;" : "=f"(r) : "f"(x)); return r;
}
__device__ __forceinline__ float fsig(float z) { return frcp(1.0f + fex2(-L2E * z)); }
__device__ __forceinline__ float fexp(float z) { return fex2(L2E * z); }

__device__ __forceinline__ uint32_t smem_u32(const void* p) {
    return (uint32_t)__cvta_generic_to_shared(p);
}

// ================= single fused kernel =================
__global__ __launch_bounds__(TMAIN) void k_all(const float* __restrict__ x,
                                               const float* __restrict__ t,
                                               float* __restrict__ out,
                                               int N, int ncells, int out_size) {
    __shared__ float tile[2 * TILEF];
    __shared__ float s_wsum[16];
    __shared__ int   s_misc;
    __shared__ double s_d[16];
    __shared__ float  acc[6];
    __shared__ int    s_nobj;

    const int tid = threadIdx.x;
    const int bx0 = blockIdx.x;

    if (bx0 == 0) {
        // -------- setup (block 0; hidden under the transform blocks) --------
        const int n = tid;
        if (n == 0) s_misc = 0;

        int cells[4] = {-1, -1, -1, -1};
        int mycell = -1;

        if (n < N) {
            const float* tn = t + 6 * n;
            int   img = (int)tn[0];
            float gx = tn[1] * (float)WW;
            float gy = tn[2] * (float)HH;
            float gw = tn[3] * (float)WW;
            float gh = tn[4] * (float)HH;
            int   lab = (int)tn[5];

            float iou[AN];
            int best = 0;
            #pragma unroll
            for (int a = 0; a < AN; a++) {
                float aw2 = c_aw[a], ah2 = c_ah[a];
                float inter = fminf(aw2, gw) * fminf(ah2, gh);
                iou[a] = inter / (aw2 * ah2 + 1e-16f + gw * gh - inter);
            }
            if (iou[1] > iou[best]) best = 1;
            if (iou[2] > iou[best]) best = 2;

            int gi = (int)gx;
            int gj = (int)gy;
            mycell = ((img * AN + best) * HH + gj) * WW + gi;

            g_cell[n] = mycell;
            g_tx[n]   = gx - floorf(gx);
            g_ty[n]   = gy - floorf(gy);
            g_tw[n]   = logf(gw / c_aw[best] + 1e-16f);
            g_th[n]   = logf(gh / c_ah[best] + 1e-16f);
            g_lab[n]  = lab;

            cells[0] = mycell;
            #pragma unroll
            for (int a = 0; a < AN; a++)
                if (iou[a] > 0.5f)
                    cells[a + 1] = ((img * AN + a) * HH + gj) * WW + gi;

            #pragma unroll
            for (int k = 0; k < 4; k++) {
                g_mcell[4 * n + k] = cells[k];
                if (cells[k] >= 0) g_mask_i[cells[k]] = 0;   // re-init each replay
            }
        } else if (n < MAXN) {
            #pragma unroll
            for (int k = 0; k < 4; k++) g_mcell[4 * n + k] = -1;
        }
        __syncthreads();

        if (n < MAXN) {
            #pragma unroll
            for (int k = 0; k < 4; k++) {
                unsigned char w = 0;
                if (cells[k] >= 0 && atomicExch(&g_mask_i[cells[k]], 1) == 0) {
                    w = 1; atomicAdd(&s_misc, 1);
                }
                g_mwin[4 * n + k] = w;
            }
        }
        __syncthreads();

        if (n < N) atomicMax(&g_mask_i[mycell], 2 + n);
        __syncthreads();
        if (n < N) g_owin[n] = (g_mask_i[mycell] == 2 + n);
        if (n == 0) g_mcnt = s_misc;
    } else {
        // -------- transform: 2 rows per block, split bulk/special paths --------
        const int bx = bx0 - 1;
        const int hp = bx % (HH / 2);
        const int a  = (bx / (HH / 2)) % AN;
        const int b  = bx / ((HH / 2) * AN);
        const int h0 = hp * 2;

        const float aw = c_aw[a], ah = c_ah[a];
        const float* __restrict__ plane =
            x + ((size_t)(b * AN + a) * NCH) * HWSZ;

        float lsum = 0.0f;

        // ---- special path address (c<5), loaded first to hide latency ----
        const bool isSpec = (tid >= SPEC0);
        int sr = 0, scc = 0, sw0 = 0;
        float4 sv;
        if (isSpec) {
            int s = tid - SPEC0;                 // [0,130)
            sr  = s / (5 * ROWF4);               // 0 or 1
            int rem = s - sr * (5 * ROWF4);
            scc = rem / ROWF4;                   // 0..4
            sw0 = (rem - scc * ROWF4) * 4;
            sv = *reinterpret_cast<const float4*>(
                plane + (size_t)scc * HWSZ + (size_t)(h0 + sr) * WW + sw0);
        }

        // ---- bulk path: 4 units each, threads 0..31 get a 5th ----
        int br[5], bc[5], bw[5];
        float4 bv[5];
        const bool hasX = (tid < BULKN - 4 * TMAIN);   // tid < 32
        #pragma unroll
        for (int k = 0; k < 4; k++) {
            int g = tid + k * TMAIN;
            int r = g / (80 * ROWF4);
            int rem = g - r * (80 * ROWF4);
            int c5 = rem / ROWF4;
            br[k] = r; bc[k] = 5 + c5; bw[k] = (rem - c5 * ROWF4) * 4;
            bv[k] = *reinterpret_cast<const float4*>(
                plane + (size_t)bc[k] * HWSZ + (size_t)(h0 + r) * WW + bw[k]);
        }
        if (hasX) {
            int g = tid + 4 * TMAIN;             // 2048 + tid
            int r = g / (80 * ROWF4);
            int rem = g - r * (80 * ROWF4);
            int c5 = rem / ROWF4;
            br[4] = r; bc[4] = 5 + c5; bw[4] = (rem - c5 * ROWF4) * 4;
            bv[4] = *reinterpret_cast<const float4*>(
                plane + (size_t)bc[4] * HWSZ + (size_t)(h0 + r) * WW + bw[4]);
        }

        // ---- bulk process: branchless ----
        #pragma unroll
        for (int k = 0; k < 4; k++) {
            float* trow = tile + br[k] * TILEF;
            int base = bw[k] * NCH + bc[k];
            trow[base]           = fsig(bv[k].x);
            trow[base + NCH]     = fsig(bv[k].y);
            trow[base + 2 * NCH] = fsig(bv[k].z);
            trow[base + 3 * NCH] = fsig(bv[k].w);
        }
        if (hasX) {
            float* trow = tile + br[4] * TILEF;
            int base = bw[4] * NCH + bc[4];
            trow[base]           = fsig(bv[4].x);
            trow[base + NCH]     = fsig(bv[4].y);
            trow[base + 2 * NCH] = fsig(bv[4].z);
            trow[base + 3 * NCH] = fsig(bv[4].w);
        }

        // ---- special process (130 threads, branchy but tiny) ----
        if (isSpec) {
            float* trow = tile + sr * TILEF;
            const float hf = (float)(h0 + sr);
            float e0, e1, e2, e3;
            if (scc == 0) {
                e0 = (fsig(sv.x) + (float)sw0) * 8.0f;
                e1 = (fsig(sv.y) + (float)(sw0 + 1)) * 8.0f;
                e2 = (fsig(sv.z) + (float)(sw0 + 2)) * 8.0f;
                e3 = (fsig(sv.w) + (float)(sw0 + 3)) * 8.0f;
            } else if (scc == 1) {
                e0 = (fsig(sv.x) + hf) * 8.0f;
                e1 = (fsig(sv.y) + hf) * 8.0f;
                e2 = (fsig(sv.z) + hf) * 8.0f;
                e3 = (fsig(sv.w) + hf) * 8.0f;
            } else if (scc == 2) {
                e0 = fexp(sv.x) * aw; e1 = fexp(sv.y) * aw;
                e2 = fexp(sv.z) * aw; e3 = fexp(sv.w) * aw;
            } else if (scc == 3) {
                e0 = fexp(sv.x) * ah; e1 = fexp(sv.y) * ah;
                e2 = fexp(sv.z) * ah; e3 = fexp(sv.w) * ah;
            } else { // scc == 4: conf channel + unconditional noobj BCE (lg2 units)
                e0 = fsig(sv.x); e1 = fsig(sv.y); e2 = fsig(sv.z); e3 = fsig(sv.w);
                lsum += flg2(1.0f - e0) + flg2(1.0f - e1)
                      + flg2(1.0f - e2) + flg2(1.0f - e3);
            }
            int base = sw0 * NCH + scc;
            trow[base]           = e0;
            trow[base + NCH]     = e1;
            trow[base + 2 * NCH] = e2;
            trow[base + 3 * NCH] = e3;
        }

        // ---- block reduce of lg2 partial ----
        #pragma unroll
        for (int off = 16; off; off >>= 1)
            lsum += __shfl_down_sync(0xffffffffu, lsum, off);
        if ((tid & 31) == 0) s_wsum[tid >> 5] = lsum;
        __syncthreads();

        if (tid == 0) {
            float fs = 0.0f;
            #pragma unroll
            for (int w = 11; w < 16; w++) fs += s_wsum[w];   // only warps 11-15 have c==4 lanes
            g_psum[bx] = fs;

            // ---- bulk async copy-out: one instruction for 35,360 bytes ----
            asm volatile("fence.proxy.async.shared::cta;" ::: "memory");
            float* gdst = out + ((size_t)(b * AN + a) * HWSZ + (size_t)h0 * WW) * NCH;
            uint32_t saddr = smem_u32(tile);
            asm volatile(
                "cp.async.bulk.global.shared::cta.bulk_group [%0], [%1], %2;"
                :: "l"(gdst), "r"(saddr), "r"((uint32_t)TILE_BYTES) : "memory");
            asm volatile("cp.async.bulk.commit_group;" ::: "memory");
            asm volatile("cp.async.bulk.wait_group 0;" ::: "memory");
        }
    }

    // -------- last-block election --------
    __syncthreads();
    if (tid == 0) {
        __threadfence();                              // release g_psum / setup data
        s_misc = (atomicAdd(&g_done, 1u) == (unsigned)(gridDim.x - 1));
    }
    __syncthreads();
    if (!s_misc) return;

    // -------- finalize (winning block only) --------
    if (tid == 0) __threadfence();                    // acquire side
    __syncthreads();
    {
        const int nblk = (int)gridDim.x - 1;

        if (tid == 0) { acc[0]=acc[1]=acc[2]=acc[3]=acc[4]=acc[5]=0.0f; s_nobj = 0; }
        __syncthreads();

        double dsum = 0.0;
        for (int i = tid; i < nblk; i += TMAIN) dsum += (double)g_psum[i];

        float fsub = 0.0f;
        #pragma unroll
        for (int k = 0; k < 2; k++) {
            int e = tid + k * TMAIN;
            if (e < 4 * MAXN && g_mwin[e]) {
                int cell = g_mcell[e];
                int i  = cell % WW;
                int j  = (cell / WW) % HH;
                int aa = (cell / HWSZ) % AN;
                int bb = cell / (AN * HWSZ);
                float z4 = x[((size_t)((bb * AN + aa) * NCH) + 4) * HWSZ
                             + (size_t)j * WW + i];
                fsub += flg2(1.0f - fsig(z4));
            }
        }
        dsum -= (double)fsub;
        #pragma unroll
        for (int off = 16; off; off >>= 1)
            dsum += __shfl_down_sync(0xffffffffu, dsum, off);
        if ((tid & 31) == 0) s_d[tid >> 5] = dsum;

        if (tid < N && g_owin[tid]) {
            int cell = g_cell[tid];
            int i  = cell % WW;
            int j  = (cell / WW) % HH;
            int aa = (cell / HWSZ) % AN;
            int bb = cell / (AN * HWSZ);
            const float* xb2 = x + ((size_t)(bb * AN + aa) * NCH) * HWSZ
                                 + (size_t)j * WW + i;
            float z0 = xb2[0];
            float z2 = xb2[(size_t)2 * HWSZ];
            float z4 = xb2[(size_t)4 * HWSZ];
            float cx = fsig(z0);
            float dx = cx - g_tx[tid];
            float dy = cx - g_ty[tid];        // reference bug: y-loss uses cx
            float dw = z2 - g_tw[tid];
            float dh = z2 - g_th[tid];        // reference bug: h-loss uses pw
            float p4 = fmaxf(fsig(z4), 1e-12f);
            float conf = -flg2(p4) * LN2;     // t=1 at obj cell
            int lab = g_lab[tid];
            float cls = 0.0f;
            #pragma unroll 4
            for (int c = 0; c < NC; c++) {
                float p = fmaxf(fsig(xb2[(size_t)(5 + c) * HWSZ]), 1e-12f);
                cls -= (c == lab) ? flg2(p) * LN2 : flg2(1.0f - p) * LN2;
            }
            atomicAdd(&acc[0], dx * dx);
            atomicAdd(&acc[1], dy * dy);
            atomicAdd(&acc[2], dw * dw);
            atomicAdd(&acc[3], dh * dh);
            atomicAdd(&acc[4], conf);
            atomicAdd(&acc[5], cls);
            atomicAdd(&s_nobj, 1);
        }
        __syncthreads();
        if (tid == 0) {
            double net = 0.0;
            #pragma unroll
            for (int w = 0; w < 16; w++) net += s_d[w];
            float nobj = fmaxf((float)s_nobj, 1.0f);
            float nno  = fmaxf((float)(ncells - g_mcnt), 1.0f);
            float noobj_bce = (float)(-(double)LN2 * net / (double)nno);
            float total = (acc[0] + acc[1] + acc[2] + acc[3]) / nobj
                        + 1.0f * (acc[4] / nobj)
                        + 0.5f * noobj_bce
                        + acc[5] / (nobj * (float)NC);
            out[out_size - 1] = total;
            g_done = 0u;                      // reset for next replay
        }
    }
}

// ---------------- launcher ----------------
extern "C" void kernel_launch(void* const* d_in, const int* in_sizes, int n_in,
                              void* d_out, int out_size) {
    const float* x   = (const float*)d_in[0];
    const float* tgt = (const float*)d_in[1];
    float* out = (float*)d_out;

    int B = in_sizes[0] / (AN * NCH * HWSZ);   // 16
    int N = in_sizes[1] / 6;                   // 256
    int nblk = B * AN * (HH / 2);              // 1248
    int ncells = B * AN * HWSZ;                // 129792

    k_all<<<nblk + 1, TMAIN>>>(x, tgt, out, N, ncells, out_size);
}